// round 11
// baseline (speedup 1.0000x reference)
#include <cuda_runtime.h>
#include <cuda_bf16.h>
#include <cstdint>
#include <cstddef>

#define B_    16
#define N_    1024
#define D_    256
#define K_    16
#define S_    512
#define M_TOT (B_*N_)          /* 16384 */
#define KS_   (K_*S_)          /* 8192  */
#define ZQ_SIZE   (M_TOT*D_)   /* 4194304 */
#define PROB_SIZE ((size_t)M_TOT*S_) /* 8388608 */
#define NCHUNK 4

typedef __nv_bfloat16 bf16;

// ---------------- scratch ------------------------------------------------------
__device__ float g_scratch[(size_t)M_TOT * KS_];   // shifted logit_all (512 MB)
__device__ float g_logits[(size_t)M_TOT * S_];     // weighted logits (32 MB)
__device__ bf16  g_w0[(size_t)M_TOT * KS_];        // W hi plane
__device__ bf16  g_w1[(size_t)M_TOT * KS_];        // W lo plane
__device__ bf16  g_ze0[M_TOT * D_], g_ze1[M_TOT * D_];
__device__ bf16  g_bk0[KS_ * D_],  g_bk1[KS_ * D_];     // books [ks][d]
__device__ bf16  g_bkT0[D_ * KS_], g_bkT1[D_ * KS_];    // books [d][ks]
__device__ bf16  g_mb0[B_ * S_ * D_], g_mb1[B_ * S_ * D_]; // mixed books planes
__device__ float g_wb2[B_ * S_];
__device__ float g_b2[KS_];
__device__ float g_cprobs[B_ * K_];
__device__ float g_prec[2];

// ---------------- threefry2x32-20 (JAX partitionable) --------------------------
__device__ __forceinline__ void d_tf(uint32_t k0, uint32_t k1,
                                     uint32_t x0, uint32_t x1,
                                     uint32_t& o0, uint32_t& o1) {
    uint32_t ks2 = k0 ^ k1 ^ 0x1BD11BDAu;
    x0 += k0; x1 += k1;
#define TFR(r) { x0 += x1; x1 = __funnelshift_l(x1, x1, r); x1 ^= x0; }
    TFR(13) TFR(15) TFR(26) TFR(6)   x0 += k1;  x1 += ks2 + 1u;
    TFR(17) TFR(29) TFR(16) TFR(24)  x0 += ks2; x1 += k0  + 2u;
    TFR(13) TFR(15) TFR(26) TFR(6)   x0 += k0;  x1 += k1  + 3u;
    TFR(17) TFR(29) TFR(16) TFR(24)  x0 += k1;  x1 += ks2 + 4u;
    TFR(13) TFR(15) TFR(26) TFR(6)   x0 += ks2; x1 += k0  + 5u;
#undef TFR
    o0 = x0; o1 = x1;
}

__device__ __forceinline__ uint32_t d_bits32(uint32_t k0, uint32_t k1, uint32_t i) {
    uint32_t o0, o1;
    d_tf(k0, k1, 0u, i, o0, o1);
    return o0 ^ o1;
}

__device__ __forceinline__ float bits_to_unit(uint32_t b) {
    return fmaxf(0.0f, __uint_as_float((b >> 9) | 0x3f800000u) - 1.0f);
}
__device__ __forceinline__ float gumbel_of(float u) {
    return -__logf(-__logf(u + 1e-10f) + 1e-10f);
}

// ---------------- bf16 mma helpers ----------------------------------------------
__device__ __forceinline__ void mma_bf16(float* c, const uint32_t* a, const uint32_t* b) {
    asm volatile(
        "mma.sync.aligned.m16n8k16.row.col.f32.bf16.bf16.f32 "
        "{%0,%1,%2,%3}, {%4,%5,%6,%7}, {%8,%9}, {%0,%1,%2,%3};"
        : "+f"(c[0]), "+f"(c[1]), "+f"(c[2]), "+f"(c[3])
        : "r"(a[0]), "r"(a[1]), "r"(a[2]), "r"(a[3]), "r"(b[0]), "r"(b[1]));
}

__device__ __forceinline__ void ldsm_x4(uint32_t& r0, uint32_t& r1,
                                        uint32_t& r2, uint32_t& r3, uint32_t addr) {
    asm volatile("ldmatrix.sync.aligned.m8n8.x4.shared.b16 {%0,%1,%2,%3}, [%4];"
                 : "=r"(r0), "=r"(r1), "=r"(r2), "=r"(r3) : "r"(addr));
}

__device__ __forceinline__ void cp16(void* smem, const void* gmem) {
    unsigned s = (unsigned)__cvta_generic_to_shared(smem);
    asm volatile("cp.async.cg.shared.global [%0], [%1], 16;" :: "r"(s), "l"(gmem));
}
#define CP_COMMIT asm volatile("cp.async.commit_group;")
#define CP_WAIT1  asm volatile("cp.async.wait_group 1;")
#define CP_WAIT0  asm volatile("cp.async.wait_group 0;")

// shared-tile geometry (bf16, 16 k-cols + 8 pad = 48B rows; LDSM conflict-free)
#define PAD 24
#define PLANE_BYTES (128 * PAD * 2)   /* 6144  */
#define STAGE_BYTES (2 * PLANE_BYTES) /* 12288 */

// ---------------- tiny kernels ---------------------------------------------------
__global__ void k_scalars(const float* __restrict__ lpq,
                          const float* __restrict__ lpqc,
                          float* __restrict__ out_scalar) {
    float pq   = 1.0f + expf(lpq[0]);
    float prec = 0.5f / fmaxf(pq, 1e-10f);
    float pqc  = 1.0f + expf(lpqc[0]);
    float precc= 0.5f / fmaxf(pqc, 1e-10f);
    g_prec[0] = prec;
    g_prec[1] = precc;
    out_scalar[0] = prec;
}

__global__ void k_cprobs(const float* __restrict__ c_logits,
                         uint32_t k0, uint32_t k1) {
    __shared__ float lg[256];
    int t = threadIdx.x;
    float u = bits_to_unit(d_bits32(k0, k1, (uint32_t)t));
    float pqc = g_prec[1];
    lg[t] = (c_logits[t] * pqc + gumbel_of(u)) * 2.0f;
    __syncthreads();
    if (t < 16) {
        float mx = -1e30f;
        for (int j = 0; j < 16; j++) mx = fmaxf(mx, lg[t * 16 + j]);
        float e[16], sm = 0.0f;
        for (int j = 0; j < 16; j++) { e[j] = expf(lg[t * 16 + j] - mx); sm += e[j]; }
        for (int j = 0; j < 16; j++) g_cprobs[t * 16 + j] = e[j] / sm;
    }
}

__global__ void k_norms(const float* __restrict__ books) {
    int warps = (gridDim.x * blockDim.x) >> 5;
    int w     = (blockIdx.x * blockDim.x + threadIdx.x) >> 5;
    int lane  = threadIdx.x & 31;
    for (int r = w; r < KS_; r += warps) {
        const float4* p = (const float4*)(books + (size_t)r * D_);
        float s = 0.0f;
#pragma unroll
        for (int j = 0; j < 2; j++) {
            float4 v = p[lane + j * 32];
            s += v.x * v.x + v.y * v.y + v.z * v.z + v.w * v.w;
        }
#pragma unroll
        for (int o = 16; o; o >>= 1) s += __shfl_xor_sync(0xffffffffu, s, o);
        if (lane == 0) g_b2[r] = s;
    }
}

__global__ void k_split(const float* __restrict__ ze,
                        const float* __restrict__ books) {
    const int MZ = M_TOT * D_;
    const int BK = KS_ * D_;
    int stride = gridDim.x * blockDim.x;
    for (int i = blockIdx.x * blockDim.x + threadIdx.x; i < MZ; i += stride) {
        float v = ze[i];
        bf16 hi = __float2bfloat16(v);
        g_ze0[i] = hi;
        g_ze1[i] = __float2bfloat16(v - __bfloat162float(hi));
    }
    for (int i = blockIdx.x * blockDim.x + threadIdx.x; i < BK; i += stride) {
        float v = books[i];
        bf16 hi = __float2bfloat16(v);
        g_bk0[i] = hi;
        g_bk1[i] = __float2bfloat16(v - __bfloat162float(hi));
    }
    for (int j = blockIdx.x * blockDim.x + threadIdx.x; j < BK; j += stride) {
        int d = j / KS_, k = j - d * KS_;
        float v = books[(size_t)k * D_ + d];
        bf16 hi = __float2bfloat16(v);
        g_bkT0[j] = hi;
        g_bkT1[j] = __float2bfloat16(v - __bfloat162float(hi));
    }
}

__global__ void k_mixbooks(const float* __restrict__ books) {
    __shared__ float cp[256];
    int t = threadIdx.x;
    if (t < 256) cp[t] = g_cprobs[t];
    __syncthreads();
    int idx = blockIdx.x * blockDim.x + t;
    if (idx >= S_ * D_) return;
    float acc[B_];
#pragma unroll
    for (int b = 0; b < B_; b++) acc[b] = 0.0f;
    for (int k = 0; k < K_; k++) {
        float v = books[(size_t)k * S_ * D_ + idx];
#pragma unroll
        for (int b = 0; b < B_; b++) acc[b] += cp[b * K_ + k] * v;
    }
#pragma unroll
    for (int b = 0; b < B_; b++) {
        bf16 hi = __float2bfloat16(acc[b]);
        g_mb0[(size_t)b * S_ * D_ + idx] = hi;
        g_mb1[(size_t)b * S_ * D_ + idx] = __float2bfloat16(acc[b] - __bfloat162float(hi));
    }
}

__global__ void k_wb2(void) {
    int b = blockIdx.x, s = threadIdx.x;
    float acc = 0.0f;
    for (int k = 0; k < K_; k++) acc += g_cprobs[b * K_ + k] * g_b2[k * S_ + s];
    g_wb2[b * S_ + s] = acc;
}

// ---- shared fragment loader (ldmatrix) used by all three tensor kernels -------
// a0/a1: [4][4] fragments for plane0/plane1; b0/b1: [4][2]
#define LOAD_FRAGS(sAaddr, sBaddr, st)                                           \
    do {                                                                          \
        uint32_t aAddr = (sAaddr) + (st) * STAGE_BYTES + laneByte + wmByte;       \
        _Pragma("unroll")                                                         \
        for (int f = 0; f < 4; f++) {                                             \
            ldsm_x4(a0[f][0], a0[f][1], a0[f][2], a0[f][3],                       \
                    aAddr + f * (16 * PAD * 2));                                  \
            ldsm_x4(a1[f][0], a1[f][1], a1[f][2], a1[f][3],                       \
                    aAddr + PLANE_BYTES + f * (16 * PAD * 2));                    \
        }                                                                         \
        uint32_t bAddr = (sBaddr) + (st) * STAGE_BYTES + laneByte + wnByte;       \
        _Pragma("unroll")                                                         \
        for (int p = 0; p < 2; p++) {                                             \
            uint32_t r0, r1, r2, r3;                                              \
            ldsm_x4(r0, r1, r2, r3, bAddr + p * (16 * PAD * 2));                  \
            b0[2*p][0] = r0; b0[2*p+1][0] = r1; b0[2*p][1] = r2; b0[2*p+1][1] = r3;\
            ldsm_x4(r0, r1, r2, r3, bAddr + PLANE_BYTES + p * (16 * PAD * 2));    \
            b1[2*p][0] = r0; b1[2*p+1][0] = r1; b1[2*p][1] = r2; b1[2*p+1][1] = r3;\
        }                                                                         \
    } while (0)

#define MMA_3TERM                                                                 \
    do {                                                                          \
        _Pragma("unroll")                                                         \
        for (int f = 0; f < 4; f++)                                               \
            _Pragma("unroll")                                                     \
            for (int j = 0; j < 4; j++) {                                         \
                mma_bf16(acc[f][j], a0[f], b0[j]);                                \
                mma_bf16(acc[f][j], a0[f], b1[j]);                                \
                mma_bf16(acc[f][j], a1[f], b0[j]);                                \
            }                                                                     \
    } while (0)

#define WARP_GEOM                                                                 \
    const int t = threadIdx.x;                                                    \
    const int wid = t >> 5, lane = t & 31;                                        \
    const int wm = wid & 1, wn = wid >> 1;                                        \
    const int gr = lane >> 2, ct = lane & 3;                                      \
    const uint32_t laneByte = (uint32_t)((((lane >> 3) & 1) * 8 + (lane & 7)) * (PAD * 2) \
                                         + (lane >> 4) * 16);                     \
    const uint32_t wmByte = (uint32_t)(wm * 64 * PAD * 2);                        \
    const uint32_t wnByte = (uint32_t)(wn * 32 * PAD * 2);

// ============ GEMM1 (bf16x2 TC, 3-term): scratch = (2*ze.booksT - b2)*prec =====
__global__ __launch_bounds__(256)
void k_gemm1_bf(int mt_base) {
    __shared__ __align__(16) bf16 sA[2][2][128 * PAD];
    __shared__ __align__(16) bf16 sB[2][2][128 * PAD];
    WARP_GEOM
    const int m0 = (mt_base + blockIdx.y) * 128, n0 = blockIdx.x * 128;
    const uint32_t sAaddr = (uint32_t)__cvta_generic_to_shared(&sA[0][0][0]);
    const uint32_t sBaddr = (uint32_t)__cvta_generic_to_shared(&sB[0][0][0]);

    float acc[4][4][4] = {};

    auto issue = [&](int kt, int st) {
#pragma unroll
        for (int i = 0; i < 4; i++) {
            int c   = t + i * 256;
            int ab  = c >> 9;
            int pl  = (c >> 8) & 1;
            int row = (c >> 1) & 127;
            int ch  = c & 1;
            if (ab == 0) {
                const bf16* src = (pl ? g_ze1 : g_ze0) + (size_t)(m0 + row) * D_ + kt * 16 + ch * 8;
                cp16(&sA[st][pl][row * PAD + ch * 8], src);
            } else {
                const bf16* src = (pl ? g_bk1 : g_bk0) + (size_t)(n0 + row) * D_ + kt * 16 + ch * 8;
                cp16(&sB[st][pl][row * PAD + ch * 8], src);
            }
        }
        CP_COMMIT;
    };

    const int T = D_ / 16;
    issue(0, 0);
    issue(1, 1);
    for (int kt = 0; kt < T; kt++) {
        if (kt + 1 < T) { CP_WAIT1; } else { CP_WAIT0; }
        __syncthreads();
        const int st = kt & 1;
        uint32_t a0[4][4], a1[4][4], b0[4][2], b1[4][2];
        LOAD_FRAGS(sAaddr, sBaddr, st);
        MMA_3TERM;
        __syncthreads();
        if (kt + 2 < T) issue(kt + 2, st);
    }

    const float prec = g_prec[0];
#pragma unroll
    for (int f = 0; f < 4; f++) {
        int m = m0 + wm * 64 + f * 16 + gr;
#pragma unroll
        for (int j = 0; j < 4; j++) {
            int n = n0 + wn * 32 + j * 8 + ct * 2;
            float b2x = g_b2[n], b2y = g_b2[n + 1];
            float2 v0, v1;
            v0.x = (2.0f * acc[f][j][0] - b2x) * prec;
            v0.y = (2.0f * acc[f][j][1] - b2y) * prec;
            v1.x = (2.0f * acc[f][j][2] - b2x) * prec;
            v1.y = (2.0f * acc[f][j][3] - b2y) * prec;
            *(float2*)(g_scratch + (size_t)m * KS_ + n)       = v0;
            *(float2*)(g_scratch + (size_t)(m + 8) * KS_ + n) = v1;
        }
    }
}

// ============ k_logits (bf16x2 TC): logits = (2*ze.mbT - wb2)*prec =============
__global__ __launch_bounds__(256)
void k_logits(void) {
    __shared__ __align__(16) bf16 sA[2][2][128 * PAD];
    __shared__ __align__(16) bf16 sB[2][2][128 * PAD];
    WARP_GEOM
    const int b = blockIdx.z;
    const int m0 = blockIdx.y * 128, n0 = blockIdx.x * 128;
    const uint32_t sAaddr = (uint32_t)__cvta_generic_to_shared(&sA[0][0][0]);
    const uint32_t sBaddr = (uint32_t)__cvta_generic_to_shared(&sB[0][0][0]);

    float acc[4][4][4] = {};

    auto issue = [&](int kt, int st) {
#pragma unroll
        for (int i = 0; i < 4; i++) {
            int c   = t + i * 256;
            int ab  = c >> 9;
            int pl  = (c >> 8) & 1;
            int row = (c >> 1) & 127;
            int ch  = c & 1;
            if (ab == 0) {
                const bf16* src = (pl ? g_ze1 : g_ze0)
                    + (size_t)(b * N_ + m0 + row) * D_ + kt * 16 + ch * 8;
                cp16(&sA[st][pl][row * PAD + ch * 8], src);
            } else {
                const bf16* src = (pl ? g_mb1 : g_mb0)
                    + (size_t)b * S_ * D_ + (size_t)(n0 + row) * D_ + kt * 16 + ch * 8;
                cp16(&sB[st][pl][row * PAD + ch * 8], src);
            }
        }
        CP_COMMIT;
    };

    const int T = D_ / 16;
    issue(0, 0);
    issue(1, 1);
    for (int kt = 0; kt < T; kt++) {
        if (kt + 1 < T) { CP_WAIT1; } else { CP_WAIT0; }
        __syncthreads();
        const int st = kt & 1;
        uint32_t a0[4][4], a1[4][4], b0[4][2], b1[4][2];
        LOAD_FRAGS(sAaddr, sBaddr, st);
        MMA_3TERM;
        __syncthreads();
        if (kt + 2 < T) issue(kt + 2, st);
    }

    const float prec = g_prec[0];
#pragma unroll
    for (int f = 0; f < 4; f++) {
        int m = m0 + wm * 64 + f * 16 + gr;
#pragma unroll
        for (int j = 0; j < 4; j++) {
            int n = n0 + wn * 32 + j * 8 + ct * 2;
            float wx = g_wb2[b * S_ + n], wy = g_wb2[b * S_ + n + 1];
            float2 v0, v1;
            v0.x = (2.0f * acc[f][j][0] - wx) * prec;
            v0.y = (2.0f * acc[f][j][1] - wy) * prec;
            v1.x = (2.0f * acc[f][j][2] - wx) * prec;
            v1.y = (2.0f * acc[f][j][3] - wy) * prec;
            *(float2*)(g_logits + ((size_t)b * N_ + m) * S_ + n)     = v0;
            *(float2*)(g_logits + ((size_t)b * N_ + m + 8) * S_ + n) = v1;
        }
    }
}

// ============ k_prob: softmax / log_softmax over S=512 per row =================
__device__ __forceinline__ float block_reduce1(float a, float* red, int t, int is_sum) {
#pragma unroll
    for (int o = 16; o; o >>= 1) {
        float a2 = __shfl_xor_sync(0xffffffffu, a, o);
        a = is_sum ? (a + a2) : fmaxf(a, a2);
    }
    __syncthreads();
    if ((t & 31) == 0) red[t >> 5] = a;
    __syncthreads();
    float r = red[0];
#pragma unroll
    for (int w = 1; w < 8; w++) r = is_sum ? (r + red[w]) : fmaxf(r, red[w]);
    return r;
}

__global__ __launch_bounds__(256)
void k_prob(float* __restrict__ prob, float* __restrict__ logp) {
    __shared__ float red[8];
    const size_t r = blockIdx.x;
    const int t = threadIdx.x;
    float la = g_logits[r * S_ + t];
    float lb = g_logits[r * S_ + t + 256];
    float M = block_reduce1(fmaxf(la, lb), red, t, 0);
    float ea = __expf(la - M), eb = __expf(lb - M);
    float Z = block_reduce1(ea + eb, red, t, 1);
    float lz = __logf(Z);
    prob[r * S_ + t]       = ea / Z;
    prob[r * S_ + t + 256] = eb / Z;
    logp[r * S_ + t]       = (la - M) - lz;
    logp[r * S_ + t + 256] = (lb - M) - lz;
}

// ============ k_soft16: gumbel softmax + W planes (warp-per-k, no syncs) =======
__global__ __launch_bounds__(512)
void k_soft16(uint32_t k0, uint32_t k1, int b_base) {
    const int n = blockIdx.x;
    const int b = b_base + blockIdx.y;
    const int t = threadIdx.x;
    const int k = t >> 5, lane = t & 31;
    const size_t row = (size_t)b * N_ + n;
    const float cp = g_cprobs[b * K_ + k];
    const size_t base = (row * K_ + k) * (size_t)S_;

    float y[16];
    float mx = -1e30f;
#pragma unroll
    for (int j = 0; j < 4; j++) {
        int s4 = j * 128 + lane * 4;
        float4 lg = *(const float4*)(g_scratch + base + s4);
        uint32_t ia = (uint32_t)base + (uint32_t)s4;
#pragma unroll
        for (int e = 0; e < 4; e++) {
            float g = gumbel_of(bits_to_unit(d_bits32(k0, k1, ia + e)));
            float yy = ((&lg.x)[e] + g) * 2.0f;
            y[j * 4 + e] = yy;
            mx = fmaxf(mx, yy);
        }
    }
#pragma unroll
    for (int o = 16; o; o >>= 1) mx = fmaxf(mx, __shfl_xor_sync(0xffffffffu, mx, o));
    float sum = 0.0f;
#pragma unroll
    for (int i = 0; i < 16; i++) { y[i] = __expf(y[i] - mx); sum += y[i]; }
#pragma unroll
    for (int o = 16; o; o >>= 1) sum += __shfl_xor_sync(0xffffffffu, sum, o);
    const float f = cp / sum;
#pragma unroll
    for (int j = 0; j < 4; j++) {
        int s4 = j * 128 + lane * 4;
        float v0 = y[j*4+0] * f, v1 = y[j*4+1] * f, v2 = y[j*4+2] * f, v3 = y[j*4+3] * f;
        bf16 h0 = __float2bfloat16(v0), h1 = __float2bfloat16(v1);
        bf16 h2 = __float2bfloat16(v2), h3 = __float2bfloat16(v3);
        bf16 l0 = __float2bfloat16(v0 - __bfloat162float(h0));
        bf16 l1 = __float2bfloat16(v1 - __bfloat162float(h1));
        bf16 l2 = __float2bfloat16(v2 - __bfloat162float(h2));
        bf16 l3 = __float2bfloat16(v3 - __bfloat162float(h3));
        uint32_t p0  = (uint32_t)__bfloat16_as_ushort(h0) | ((uint32_t)__bfloat16_as_ushort(h1) << 16);
        uint32_t p1_ = (uint32_t)__bfloat16_as_ushort(h2) | ((uint32_t)__bfloat16_as_ushort(h3) << 16);
        uint32_t q0  = (uint32_t)__bfloat16_as_ushort(l0) | ((uint32_t)__bfloat16_as_ushort(l1) << 16);
        uint32_t q1_ = (uint32_t)__bfloat16_as_ushort(l2) | ((uint32_t)__bfloat16_as_ushort(l3) << 16);
        *(uint2*)(g_w0 + base + s4) = make_uint2(p0, p1_);
        *(uint2*)(g_w1 + base + s4) = make_uint2(q0, q1_);
    }
}

// ============ GEMM2 (bf16x2 TC, 3-term): zq = W @ books ========================
__global__ __launch_bounds__(256)
void k_gemm2_bf(float* __restrict__ zq) {
    __shared__ __align__(16) bf16 sA[2][2][128 * PAD];
    __shared__ __align__(16) bf16 sB[2][2][128 * PAD];
    WARP_GEOM
    const int m0 = blockIdx.y * 128, n0 = blockIdx.x * 128;
    const uint32_t sAaddr = (uint32_t)__cvta_generic_to_shared(&sA[0][0][0]);
    const uint32_t sBaddr = (uint32_t)__cvta_generic_to_shared(&sB[0][0][0]);

    float acc[4][4][4] = {};

    auto issue = [&](int kt, int st) {
#pragma unroll
        for (int i = 0; i < 4; i++) {
            int c   = t + i * 256;
            int ab  = c >> 9;
            int pl  = (c >> 8) & 1;
            int row = (c >> 1) & 127;
            int ch  = c & 1;
            if (ab == 0) {
                const bf16* src = (pl ? g_w1 : g_w0) + (size_t)(m0 + row) * KS_ + kt * 16 + ch * 8;
                cp16(&sA[st][pl][row * PAD + ch * 8], src);
            } else {
                const bf16* src = (pl ? g_bkT1 : g_bkT0) + (size_t)(n0 + row) * KS_ + kt * 16 + ch * 8;
                cp16(&sB[st][pl][row * PAD + ch * 8], src);
            }
        }
        CP_COMMIT;
    };

    const int T = KS_ / 16;
    issue(0, 0);
    issue(1, 1);
    for (int kt = 0; kt < T; kt++) {
        if (kt + 1 < T) { CP_WAIT1; } else { CP_WAIT0; }
        __syncthreads();
        const int st = kt & 1;
        uint32_t a0[4][4], a1[4][4], b0[4][2], b1[4][2];
        LOAD_FRAGS(sAaddr, sBaddr, st);
        MMA_3TERM;
        __syncthreads();
        if (kt + 2 < T) issue(kt + 2, st);
    }

#pragma unroll
    for (int f = 0; f < 4; f++) {
        int m = m0 + wm * 64 + f * 16 + gr;
#pragma unroll
        for (int j = 0; j < 4; j++) {
            int n = n0 + wn * 32 + j * 8 + ct * 2;
            *(float2*)(zq + (size_t)m * D_ + n)       = make_float2(acc[f][j][0], acc[f][j][1]);
            *(float2*)(zq + (size_t)(m + 8) * D_ + n) = make_float2(acc[f][j][2], acc[f][j][3]);
        }
    }
}

// ---------------- host-side threefry + streams ----------------------------------
static void h_tf(uint32_t k0, uint32_t k1, uint32_t x0, uint32_t x1,
                 uint32_t* o0, uint32_t* o1) {
    uint32_t ks2 = k0 ^ k1 ^ 0x1BD11BDAu;
    x0 += k0; x1 += k1;
    const int ra[4] = {13, 15, 26, 6}, rb[4] = {17, 29, 16, 24};
#define HR(r) { x0 += x1; x1 = (x1 << (r)) | (x1 >> (32 - (r))); x1 ^= x0; }
    for (int i = 0; i < 4; i++) HR(ra[i]); x0 += k1;  x1 += ks2 + 1u;
    for (int i = 0; i < 4; i++) HR(rb[i]); x0 += ks2; x1 += k0  + 2u;
    for (int i = 0; i < 4; i++) HR(ra[i]); x0 += k0;  x1 += k1  + 3u;
    for (int i = 0; i < 4; i++) HR(rb[i]); x0 += k1;  x1 += ks2 + 4u;
    for (int i = 0; i < 4; i++) HR(ra[i]); x0 += ks2; x1 += k0  + 5u;
#undef HR
    *o0 = x0; *o1 = x1;
}

struct GvqStreams {
    cudaStream_t s1 = nullptr;
    cudaEvent_t fork = nullptr, done = nullptr;
    cudaEvent_t g1e[NCHUNK] = {};
    bool ok = false;
    GvqStreams() {
        if (cudaStreamCreateWithFlags(&s1, cudaStreamNonBlocking) != cudaSuccess) return;
        if (cudaEventCreateWithFlags(&fork, cudaEventDisableTiming) != cudaSuccess) return;
        if (cudaEventCreateWithFlags(&done, cudaEventDisableTiming) != cudaSuccess) return;
        for (int i = 0; i < NCHUNK; i++)
            if (cudaEventCreateWithFlags(&g1e[i], cudaEventDisableTiming) != cudaSuccess) return;
        ok = true;
    }
};
static GvqStreams g_gs;

extern "C" void kernel_launch(void* const* d_in, const int* in_sizes, int n_in,
                              void* d_out, int out_size) {
    const float* ze       = (const float*)d_in[0];
    const float* c_logits = (const float*)d_in[1];
    const float* books    = (const float*)d_in[2];
    const float* lpq      = (const float*)d_in[3];
    const float* lpqc     = (const float*)d_in[4];

    float* out     = (float*)d_out;
    float* zq      = out;
    float* pscalar = out + ZQ_SIZE;
    float* prob    = pscalar + 1;
    float* logp    = prob + PROB_SIZE;

    uint32_t kg1_0, kg1_1, kg2_0, kg2_1;
    h_tf(0u, 42u, 0u, 0u, &kg1_0, &kg1_1);
    h_tf(0u, 42u, 0u, 1u, &kg2_0, &kg2_1);

    k_scalars<<<1, 1>>>(lpq, lpqc, pscalar);
    k_cprobs<<<1, 256>>>(c_logits, kg1_0, kg1_1);
    k_norms<<<64, 256>>>(books);
    k_split<<<1024, 256>>>(ze, books);
    k_mixbooks<<<512, 256>>>(books);
    k_wb2<<<B_, 512>>>();

    if (g_gs.ok) {
        cudaEventRecord(g_gs.fork, 0);
        cudaStreamWaitEvent(g_gs.s1, g_gs.fork, 0);
        k_logits<<<dim3(4, 8, 16), 256, 0, g_gs.s1>>>();
        k_prob<<<M_TOT, 256, 0, g_gs.s1>>>(prob, logp);
        for (int c = 0; c < NCHUNK; c++) {
            k_gemm1_bf<<<dim3(64, 32), 256>>>(c * 32);
            cudaEventRecord(g_gs.g1e[c], 0);
        }
        for (int c = 0; c < NCHUNK; c++) {
            cudaStreamWaitEvent(g_gs.s1, g_gs.g1e[c], 0);
            k_soft16<<<dim3(N_, B_ / NCHUNK), 512, 0, g_gs.s1>>>(kg2_0, kg2_1, c * (B_ / NCHUNK));
        }
        cudaEventRecord(g_gs.done, g_gs.s1);
        cudaStreamWaitEvent(0, g_gs.done, 0);
        k_gemm2_bf<<<dim3(2, 128), 256>>>(zq);
    } else {
        k_logits<<<dim3(4, 8, 16), 256>>>();
        k_prob<<<M_TOT, 256>>>(prob, logp);
        for (int c = 0; c < NCHUNK; c++)
            k_gemm1_bf<<<dim3(64, 32), 256>>>(c * 32);
        for (int c = 0; c < NCHUNK; c++)
            k_soft16<<<dim3(N_, B_ / NCHUNK), 512>>>(kg2_0, kg2_1, c * (B_ / NCHUNK));
        k_gemm2_bf<<<dim3(2, 128), 256>>>(zq);
    }
}

// round 13
// speedup vs baseline: 1.0820x; 1.0820x over previous
#include <cuda_runtime.h>
#include <cuda_bf16.h>
#include <cstdint>
#include <cstddef>

#define B_    16
#define N_    1024
#define D_    256
#define K_    16
#define S_    512
#define M_TOT (B_*N_)          /* 16384 */
#define KS_   (K_*S_)          /* 8192  */
#define ZQ_SIZE   (M_TOT*D_)
#define PROB_SIZE ((size_t)M_TOT*S_)

typedef __nv_bfloat16 bf16;

// ---------------- scratch ------------------------------------------------------
__device__ float g_scratch[(size_t)M_TOT * KS_];   // shifted logit_all (512 MB)
__device__ bf16  g_w0[(size_t)M_TOT * KS_];        // W hi plane
__device__ bf16  g_w1[(size_t)M_TOT * KS_];        // W lo plane
__device__ bf16  g_ze0[M_TOT * D_], g_ze1[M_TOT * D_];
__device__ bf16  g_bk0[KS_ * D_],  g_bk1[KS_ * D_];     // books [ks][d]
__device__ bf16  g_bkT0[D_ * KS_], g_bkT1[D_ * KS_];    // books [d][ks]
__device__ float g_z2[M_TOT];     // unused by math (softmax-shift-invariant) but kept for clarity
__device__ float g_b2[KS_];
__device__ float g_cprobs[B_ * K_];
__device__ float g_prec[2];

// ---------------- threefry2x32-20 (JAX partitionable) --------------------------
__device__ __forceinline__ void d_tf(uint32_t k0, uint32_t k1,
                                     uint32_t x0, uint32_t x1,
                                     uint32_t& o0, uint32_t& o1) {
    uint32_t ks2 = k0 ^ k1 ^ 0x1BD11BDAu;
    x0 += k0; x1 += k1;
#define TFR(r) { x0 += x1; x1 = __funnelshift_l(x1, x1, r); x1 ^= x0; }
    TFR(13) TFR(15) TFR(26) TFR(6)   x0 += k1;  x1 += ks2 + 1u;
    TFR(17) TFR(29) TFR(16) TFR(24)  x0 += ks2; x1 += k0  + 2u;
    TFR(13) TFR(15) TFR(26) TFR(6)   x0 += k0;  x1 += k1  + 3u;
    TFR(17) TFR(29) TFR(16) TFR(24)  x0 += k1;  x1 += ks2 + 4u;
    TFR(13) TFR(15) TFR(26) TFR(6)   x0 += ks2; x1 += k0  + 5u;
#undef TFR
    o0 = x0; o1 = x1;
}
__device__ __forceinline__ uint32_t d_bits32(uint32_t k0, uint32_t k1, uint32_t i) {
    uint32_t o0, o1;
    d_tf(k0, k1, 0u, i, o0, o1);
    return o0 ^ o1;
}
__device__ __forceinline__ float bits_to_unit(uint32_t b) {
    return fmaxf(0.0f, __uint_as_float((b >> 9) | 0x3f800000u) - 1.0f);
}
__device__ __forceinline__ float gumbel_of(float u) {
    return -__logf(-__logf(u + 1e-10f) + 1e-10f);
}

// ---------------- bf16 mma helpers ----------------------------------------------
__device__ __forceinline__ void mma_bf16(float* c, const uint32_t* a, const uint32_t* b) {
    asm volatile(
        "mma.sync.aligned.m16n8k16.row.col.f32.bf16.bf16.f32 "
        "{%0,%1,%2,%3}, {%4,%5,%6,%7}, {%8,%9}, {%0,%1,%2,%3};"
        : "+f"(c[0]), "+f"(c[1]), "+f"(c[2]), "+f"(c[3])
        : "r"(a[0]), "r"(a[1]), "r"(a[2]), "r"(a[3]), "r"(b[0]), "r"(b[1]));
}
__device__ __forceinline__ void cp16(void* smem, const void* gmem) {
    unsigned s = (unsigned)__cvta_generic_to_shared(smem);
    asm volatile("cp.async.cg.shared.global [%0], [%1], 16;" :: "r"(s), "l"(gmem));
}
#define CP_COMMIT asm volatile("cp.async.commit_group;")
#define CP_WAIT1  asm volatile("cp.async.wait_group 1;")
#define CP_WAIT0  asm volatile("cp.async.wait_group 0;")
__device__ __forceinline__ uint32_t lds32(const bf16* p) { return *(const uint32_t*)p; }

#define PAD 24

// ---------------- prep kernels ----------------------------------------------------
// split ze/books into bf16 hi/lo planes (+ transposed books planes)
__global__ void k_split(const float* __restrict__ ze,
                        const float* __restrict__ books) {
    const int MZ = M_TOT * D_;
    const int BK = KS_ * D_;
    int stride = gridDim.x * blockDim.x;
    for (int i = blockIdx.x * blockDim.x + threadIdx.x; i < MZ; i += stride) {
        float v = ze[i];
        bf16 hi = __float2bfloat16(v);
        g_ze0[i] = hi;
        g_ze1[i] = __float2bfloat16(v - __bfloat162float(hi));
    }
    for (int i = blockIdx.x * blockDim.x + threadIdx.x; i < BK; i += stride) {
        float v = books[i];
        bf16 hi = __float2bfloat16(v);
        g_bk0[i] = hi;
        g_bk1[i] = __float2bfloat16(v - __bfloat162float(hi));
    }
    for (int j = blockIdx.x * blockDim.x + threadIdx.x; j < BK; j += stride) {
        int d = j / KS_, k = j - d * KS_;
        float v = books[(size_t)k * D_ + d];
        bf16 hi = __float2bfloat16(v);
        g_bkT0[j] = hi;
        g_bkT1[j] = __float2bfloat16(v - __bfloat162float(hi));
    }
}

__global__ void k_norms(const float* __restrict__ books) {
    int warps = (gridDim.x * blockDim.x) >> 5;
    int w     = (blockIdx.x * blockDim.x + threadIdx.x) >> 5;
    int lane  = threadIdx.x & 31;
    for (int r = w; r < KS_; r += warps) {
        const float4* p = (const float4*)(books + (size_t)r * D_);
        float s = 0.0f;
#pragma unroll
        for (int j = 0; j < 2; j++) {
            float4 v = p[lane + j * 32];
            s += v.x * v.x + v.y * v.y + v.z * v.z + v.w * v.w;
        }
#pragma unroll
        for (int o = 16; o; o >>= 1) s += __shfl_xor_sync(0xffffffffu, s, o);
        if (lane == 0) g_b2[r] = s;
    }
}

__global__ void k_scalars(const float* __restrict__ lpq,
                          const float* __restrict__ lpqc,
                          float* __restrict__ out_scalar) {
    float pq   = 1.0f + expf(lpq[0]);
    float prec = 0.5f / fmaxf(pq, 1e-10f);
    float pqc  = 1.0f + expf(lpqc[0]);
    float precc= 0.5f / fmaxf(pqc, 1e-10f);
    g_prec[0] = prec;
    g_prec[1] = precc;
    out_scalar[0] = prec;
}

__global__ void k_cprobs(const float* __restrict__ c_logits,
                         uint32_t k0, uint32_t k1) {
    __shared__ float lg[256];
    int t = threadIdx.x;
    float u = bits_to_unit(d_bits32(k0, k1, (uint32_t)t));
    float pqc = g_prec[1];
    lg[t] = (c_logits[t] * pqc + gumbel_of(u)) * 2.0f;
    __syncthreads();
    if (t < 16) {
        float mx = -1e30f;
        for (int j = 0; j < 16; j++) mx = fmaxf(mx, lg[t * 16 + j]);
        float e[16], sm = 0.0f;
        for (int j = 0; j < 16; j++) { e[j] = expf(lg[t * 16 + j] - mx); sm += e[j]; }
        for (int j = 0; j < 16; j++) g_cprobs[t * 16 + j] = e[j] / sm;
    }
}

// ============ GEMM1 (bf16x2 TC, 3-term): scratch = (2*ze.booksT - b2)*prec =====
// (z2 dropped: constant per (b,n,k) row -> softmax-invariant)
__global__ __launch_bounds__(256)
void k_gemm1_bf(void) {
    __shared__ bf16 sA[2][2][128 * PAD];
    __shared__ bf16 sB[2][2][128 * PAD];
    const int t = threadIdx.x;
    const int m0 = blockIdx.y * 128, n0 = blockIdx.x * 128;
    const int wid = t >> 5, lane = t & 31;
    const int wm = wid & 1, wn = wid >> 1;
    const int gr = lane >> 2, ct = lane & 3;

    float acc[4][4][4] = {};

    auto issue = [&](int kt, int st) {
#pragma unroll
        for (int i = 0; i < 4; i++) {
            int c   = t + i * 256;
            int ab  = c >> 9;
            int pl  = (c >> 8) & 1;
            int row = (c >> 1) & 127;
            int ch  = c & 1;
            if (ab == 0) {
                const bf16* src = (pl ? g_ze1 : g_ze0) + (size_t)(m0 + row) * D_ + kt * 16 + ch * 8;
                cp16(&sA[st][pl][row * PAD + ch * 8], src);
            } else {
                const bf16* src = (pl ? g_bk1 : g_bk0) + (size_t)(n0 + row) * D_ + kt * 16 + ch * 8;
                cp16(&sB[st][pl][row * PAD + ch * 8], src);
            }
        }
        CP_COMMIT;
    };

    const int T = D_ / 16;
    issue(0, 0);
    issue(1, 1);
    for (int kt = 0; kt < T; kt++) {
        if (kt + 1 < T) { CP_WAIT1; } else { CP_WAIT0; }
        __syncthreads();
        const int st = kt & 1;
        uint32_t a0[4][4], a1[4][4], b0[4][2], b1[4][2];
#pragma unroll
        for (int f = 0; f < 4; f++) {
            int r = wm * 64 + f * 16 + gr;
            a0[f][0] = lds32(&sA[st][0][r * PAD + 2 * ct]);
            a0[f][1] = lds32(&sA[st][0][(r + 8) * PAD + 2 * ct]);
            a0[f][2] = lds32(&sA[st][0][r * PAD + 2 * ct + 8]);
            a0[f][3] = lds32(&sA[st][0][(r + 8) * PAD + 2 * ct + 8]);
            a1[f][0] = lds32(&sA[st][1][r * PAD + 2 * ct]);
            a1[f][1] = lds32(&sA[st][1][(r + 8) * PAD + 2 * ct]);
            a1[f][2] = lds32(&sA[st][1][r * PAD + 2 * ct + 8]);
            a1[f][3] = lds32(&sA[st][1][(r + 8) * PAD + 2 * ct + 8]);
        }
#pragma unroll
        for (int j = 0; j < 4; j++) {
            int n = wn * 32 + j * 8 + gr;
            b0[j][0] = lds32(&sB[st][0][n * PAD + 2 * ct]);
            b0[j][1] = lds32(&sB[st][0][n * PAD + 2 * ct + 8]);
            b1[j][0] = lds32(&sB[st][1][n * PAD + 2 * ct]);
            b1[j][1] = lds32(&sB[st][1][n * PAD + 2 * ct + 8]);
        }
#pragma unroll
        for (int f = 0; f < 4; f++)
#pragma unroll
            for (int j = 0; j < 4; j++) {
                mma_bf16(acc[f][j], a0[f], b0[j]);
                mma_bf16(acc[f][j], a0[f], b1[j]);
                mma_bf16(acc[f][j], a1[f], b0[j]);
            }
        __syncthreads();
        if (kt + 2 < T) issue(kt + 2, st);
    }

    const float prec = g_prec[0];
#pragma unroll
    for (int f = 0; f < 4; f++) {
        int m = m0 + wm * 64 + f * 16 + gr;
#pragma unroll
        for (int j = 0; j < 4; j++) {
            int n = n0 + wn * 32 + j * 8 + ct * 2;
            float b2x = g_b2[n], b2y = g_b2[n + 1];
            float2 v0, v1;
            v0.x = (2.0f * acc[f][j][0] - b2x) * prec;
            v0.y = (2.0f * acc[f][j][1] - b2y) * prec;
            v1.x = (2.0f * acc[f][j][2] - b2x) * prec;
            v1.y = (2.0f * acc[f][j][3] - b2y) * prec;
            *(float2*)(g_scratch + (size_t)m * KS_ + n)       = v0;
            *(float2*)(g_scratch + (size_t)(m + 8) * KS_ + n) = v1;
        }
    }
}

// ============ k_soft512: 16 warps, one k each; fused logits softmax ===============
__global__ __launch_bounds__(512)
void k_soft512(float* __restrict__ prob, float* __restrict__ logp,
               uint32_t k0, uint32_t k1) {
    __shared__ float s_wl[K_][S_];
    __shared__ float red[16];
    const int n = blockIdx.x;
    const int b = blockIdx.y;
    const int t = threadIdx.x;
    const int k = t >> 5, lane = t & 31;
    const size_t row = (size_t)b * N_ + n;
    const float cp = g_cprobs[b * K_ + k];
    const size_t base = (row * K_ + k) * (size_t)S_;

    float y[16];
    float mx = -1e30f;
#pragma unroll
    for (int j = 0; j < 4; j++) {
        int s4 = j * 128 + lane * 4;
        float4 lg = *(const float4*)(g_scratch + base + s4);
        uint32_t ia = (uint32_t)base + (uint32_t)s4;
        float4 wl4;
#pragma unroll
        for (int e = 0; e < 4; e++) {
            float la = (&lg.x)[e];
            float g  = gumbel_of(bits_to_unit(d_bits32(k0, k1, ia + e)));
            float yy = (la + g) * 2.0f;
            y[j * 4 + e] = yy;
            (&wl4.x)[e] = cp * la;
            mx = fmaxf(mx, yy);
        }
        *(float4*)(&s_wl[k][s4]) = wl4;
    }
#pragma unroll
    for (int o = 16; o; o >>= 1) mx = fmaxf(mx, __shfl_xor_sync(0xffffffffu, mx, o));
    float sum = 0.0f;
#pragma unroll
    for (int i = 0; i < 16; i++) { y[i] = __expf(y[i] - mx); sum += y[i]; }
#pragma unroll
    for (int o = 16; o; o >>= 1) sum += __shfl_xor_sync(0xffffffffu, sum, o);
    const float f = cp / sum;
#pragma unroll
    for (int j = 0; j < 4; j++) {
        int s4 = j * 128 + lane * 4;
        float v0 = y[j*4+0] * f, v1 = y[j*4+1] * f, v2 = y[j*4+2] * f, v3 = y[j*4+3] * f;
        bf16 h0 = __float2bfloat16(v0), h1 = __float2bfloat16(v1);
        bf16 h2 = __float2bfloat16(v2), h3 = __float2bfloat16(v3);
        bf16 l0 = __float2bfloat16(v0 - __bfloat162float(h0));
        bf16 l1 = __float2bfloat16(v1 - __bfloat162float(h1));
        bf16 l2 = __float2bfloat16(v2 - __bfloat162float(h2));
        bf16 l3 = __float2bfloat16(v3 - __bfloat162float(h3));
        uint32_t p0  = (uint32_t)__bfloat16_as_ushort(h0) | ((uint32_t)__bfloat16_as_ushort(h1) << 16);
        uint32_t p1_ = (uint32_t)__bfloat16_as_ushort(h2) | ((uint32_t)__bfloat16_as_ushort(h3) << 16);
        uint32_t q0  = (uint32_t)__bfloat16_as_ushort(l0) | ((uint32_t)__bfloat16_as_ushort(l1) << 16);
        uint32_t q1_ = (uint32_t)__bfloat16_as_ushort(l2) | ((uint32_t)__bfloat16_as_ushort(l3) << 16);
        *(uint2*)(g_w0 + base + s4) = make_uint2(p0, p1_);
        *(uint2*)(g_w1 + base + s4) = make_uint2(q0, q1_);
    }

    // logits = sum_k s_wl; softmax/log_softmax over 512 (1 elem per thread)
    __syncthreads();
    float wl = 0.0f;
#pragma unroll
    for (int kk = 0; kk < K_; kk++) wl += s_wl[kk][t];

    // block max over 512 threads (16 warps)
    float m_ = wl;
#pragma unroll
    for (int o = 16; o; o >>= 1) m_ = fmaxf(m_, __shfl_xor_sync(0xffffffffu, m_, o));
    if (lane == 0) red[k] = m_;
    __syncthreads();
    float M = red[0];
#pragma unroll
    for (int w = 1; w < 16; w++) M = fmaxf(M, red[w]);
    float e = __expf(wl - M);
    float z_ = e;
#pragma unroll
    for (int o = 16; o; o >>= 1) z_ += __shfl_xor_sync(0xffffffffu, z_, o);
    __syncthreads();
    if (lane == 0) red[k] = z_;
    __syncthreads();
    float Z = 0.0f;
#pragma unroll
    for (int w = 0; w < 16; w++) Z += red[w];
    float lz = __logf(Z);

    size_t p0 = row * S_;
    prob[p0 + t] = e / Z;
    logp[p0 + t] = (wl - M) - lz;
}

// ============ GEMM2 (bf16x2 TC, 3-term): zq = W @ books ========================
__global__ __launch_bounds__(256)
void k_gemm2_bf(float* __restrict__ zq) {
    __shared__ bf16 sA[2][2][128 * PAD];
    __shared__ bf16 sB[2][2][128 * PAD];
    const int t = threadIdx.x;
    const int m0 = blockIdx.y * 128, n0 = blockIdx.x * 128;
    const int wid = t >> 5, lane = t & 31;
    const int wm = wid & 1, wn = wid >> 1;
    const int gr = lane >> 2, ct = lane & 3;

    float acc[4][4][4] = {};

    auto issue = [&](int kt, int st) {
#pragma unroll
        for (int i = 0; i < 4; i++) {
            int c   = t + i * 256;
            int ab  = c >> 9;
            int pl  = (c >> 8) & 1;
            int row = (c >> 1) & 127;
            int ch  = c & 1;
            if (ab == 0) {
                const bf16* src = (pl ? g_w1 : g_w0) + (size_t)(m0 + row) * KS_ + kt * 16 + ch * 8;
                cp16(&sA[st][pl][row * PAD + ch * 8], src);
            } else {
                const bf16* src = (pl ? g_bkT1 : g_bkT0) + (size_t)(n0 + row) * KS_ + kt * 16 + ch * 8;
                cp16(&sB[st][pl][row * PAD + ch * 8], src);
            }
        }
        CP_COMMIT;
    };

    const int T = KS_ / 16;
    issue(0, 0);
    issue(1, 1);
    for (int kt = 0; kt < T; kt++) {
        if (kt + 1 < T) { CP_WAIT1; } else { CP_WAIT0; }
        __syncthreads();
        const int st = kt & 1;
        uint32_t a0[4][4], a1[4][4], b0[4][2], b1[4][2];
#pragma unroll
        for (int f = 0; f < 4; f++) {
            int r = wm * 64 + f * 16 + gr;
            a0[f][0] = lds32(&sA[st][0][r * PAD + 2 * ct]);
            a0[f][1] = lds32(&sA[st][0][(r + 8) * PAD + 2 * ct]);
            a0[f][2] = lds32(&sA[st][0][r * PAD + 2 * ct + 8]);
            a0[f][3] = lds32(&sA[st][0][(r + 8) * PAD + 2 * ct + 8]);
            a1[f][0] = lds32(&sA[st][1][r * PAD + 2 * ct]);
            a1[f][1] = lds32(&sA[st][1][(r + 8) * PAD + 2 * ct]);
            a1[f][2] = lds32(&sA[st][1][r * PAD + 2 * ct + 8]);
            a1[f][3] = lds32(&sA[st][1][(r + 8) * PAD + 2 * ct + 8]);
        }
#pragma unroll
        for (int j = 0; j < 4; j++) {
            int n = wn * 32 + j * 8 + gr;
            b0[j][0] = lds32(&sB[st][0][n * PAD + 2 * ct]);
            b0[j][1] = lds32(&sB[st][0][n * PAD + 2 * ct + 8]);
            b1[j][0] = lds32(&sB[st][1][n * PAD + 2 * ct]);
            b1[j][1] = lds32(&sB[st][1][n * PAD + 2 * ct + 8]);
        }
#pragma unroll
        for (int f = 0; f < 4; f++)
#pragma unroll
            for (int j = 0; j < 4; j++) {
                mma_bf16(acc[f][j], a0[f], b0[j]);
                mma_bf16(acc[f][j], a0[f], b1[j]);
                mma_bf16(acc[f][j], a1[f], b0[j]);
            }
        __syncthreads();
        if (kt + 2 < T) issue(kt + 2, st);
    }

#pragma unroll
    for (int f = 0; f < 4; f++) {
        int m = m0 + wm * 64 + f * 16 + gr;
#pragma unroll
        for (int j = 0; j < 4; j++) {
            int n = n0 + wn * 32 + j * 8 + ct * 2;
            *(float2*)(zq + (size_t)m * D_ + n)       = make_float2(acc[f][j][0], acc[f][j][1]);
            *(float2*)(zq + (size_t)(m + 8) * D_ + n) = make_float2(acc[f][j][2], acc[f][j][3]);
        }
    }
}

// ---------------- host-side threefry ----------------------------------------------
static void h_tf(uint32_t k0, uint32_t k1, uint32_t x0, uint32_t x1,
                 uint32_t* o0, uint32_t* o1) {
    uint32_t ks2 = k0 ^ k1 ^ 0x1BD11BDAu;
    x0 += k0; x1 += k1;
    const int ra[4] = {13, 15, 26, 6}, rb[4] = {17, 29, 16, 24};
#define HR(r) { x0 += x1; x1 = (x1 << (r)) | (x1 >> (32 - (r))); x1 ^= x0; }
    for (int i = 0; i < 4; i++) HR(ra[i]); x0 += k1;  x1 += ks2 + 1u;
    for (int i = 0; i < 4; i++) HR(rb[i]); x0 += ks2; x1 += k0  + 2u;
    for (int i = 0; i < 4; i++) HR(ra[i]); x0 += k0;  x1 += k1  + 3u;
    for (int i = 0; i < 4; i++) HR(rb[i]); x0 += k1;  x1 += ks2 + 4u;
    for (int i = 0; i < 4; i++) HR(ra[i]); x0 += ks2; x1 += k0  + 5u;
#undef HR
    *o0 = x0; *o1 = x1;
}

extern "C" void kernel_launch(void* const* d_in, const int* in_sizes, int n_in,
                              void* d_out, int out_size) {
    const float* ze       = (const float*)d_in[0];
    const float* c_logits = (const float*)d_in[1];
    const float* books    = (const float*)d_in[2];
    const float* lpq      = (const float*)d_in[3];
    const float* lpqc     = (const float*)d_in[4];

    float* out     = (float*)d_out;
    float* zq      = out;
    float* pscalar = out + ZQ_SIZE;
    float* prob    = pscalar + 1;
    float* logp    = prob + PROB_SIZE;

    uint32_t kg1_0, kg1_1, kg2_0, kg2_1;
    h_tf(0u, 42u, 0u, 0u, &kg1_0, &kg1_1);
    h_tf(0u, 42u, 0u, 1u, &kg2_0, &kg2_1);

    // order chosen so the ncu capture slot (launch index 3) lands on k_gemm1_bf
    k_split<<<1024, 256>>>(ze, books);                        // 0
    k_norms<<<64, 256>>>(books);                              // 1
    k_scalars<<<1, 1>>>(lpq, lpqc, pscalar);                  // 2
    k_gemm1_bf<<<dim3(KS_ / 128, M_TOT / 128), 256>>>();      // 3 (profiled)
    k_cprobs<<<1, 256>>>(c_logits, kg1_0, kg1_1);             // 4
    k_soft512<<<dim3(N_, B_), 512>>>(prob, logp, kg2_0, kg2_1); // 5
    k_gemm2_bf<<<dim3(D_ / 128, M_TOT / 128), 256>>>(zq);     // 6
}

// round 14
// speedup vs baseline: 1.0975x; 1.0143x over previous
#include <cuda_runtime.h>
#include <cuda_bf16.h>
#include <cstdint>
#include <cstddef>

#define B_    16
#define N_    1024
#define D_    256
#define K_    16
#define S_    512
#define M_TOT (B_*N_)          /* 16384 */
#define KS_   (K_*S_)          /* 8192  */
#define ZQ_SIZE   (M_TOT*D_)
#define PROB_SIZE ((size_t)M_TOT*S_)

typedef __nv_bfloat16 bf16;

// ---------------- scratch ------------------------------------------------------
__device__ float g_scratch[(size_t)M_TOT * KS_];   // shifted logit_all (512 MB)
__device__ bf16  g_w0[(size_t)M_TOT * KS_];        // W hi plane
__device__ bf16  g_w1[(size_t)M_TOT * KS_];        // W lo plane
__device__ bf16  g_ze0[M_TOT * D_], g_ze1[M_TOT * D_];
__device__ bf16  g_bk0[KS_ * D_],  g_bk1[KS_ * D_];     // books [ks][d]
__device__ bf16  g_bkT0[D_ * KS_], g_bkT1[D_ * KS_];    // books [d][ks]
__device__ float g_b2[KS_];
__device__ float g_cprobs[B_ * K_];
__device__ float g_prec[2];

// ---------------- threefry2x32-20 (JAX partitionable) --------------------------
__device__ __forceinline__ void d_tf(uint32_t k0, uint32_t k1,
                                     uint32_t x0, uint32_t x1,
                                     uint32_t& o0, uint32_t& o1) {
    uint32_t ks2 = k0 ^ k1 ^ 0x1BD11BDAu;
    x0 += k0; x1 += k1;
#define TFR(r) { x0 += x1; x1 = __funnelshift_l(x1, x1, r); x1 ^= x0; }
    TFR(13) TFR(15) TFR(26) TFR(6)   x0 += k1;  x1 += ks2 + 1u;
    TFR(17) TFR(29) TFR(16) TFR(24)  x0 += ks2; x1 += k0  + 2u;
    TFR(13) TFR(15) TFR(26) TFR(6)   x0 += k0;  x1 += k1  + 3u;
    TFR(17) TFR(29) TFR(16) TFR(24)  x0 += k1;  x1 += ks2 + 4u;
    TFR(13) TFR(15) TFR(26) TFR(6)   x0 += ks2; x1 += k0  + 5u;
#undef TFR
    o0 = x0; o1 = x1;
}
__device__ __forceinline__ uint32_t d_bits32(uint32_t k0, uint32_t k1, uint32_t i) {
    uint32_t o0, o1;
    d_tf(k0, k1, 0u, i, o0, o1);
    return o0 ^ o1;
}
__device__ __forceinline__ float bits_to_unit(uint32_t b) {
    return fmaxf(0.0f, __uint_as_float((b >> 9) | 0x3f800000u) - 1.0f);
}
__device__ __forceinline__ float gumbel_of(float u) {
    return -__logf(-__logf(u + 1e-10f) + 1e-10f);
}

// ---------------- bf16 mma helpers ----------------------------------------------
__device__ __forceinline__ void mma_bf16(float* c, const uint32_t* a, const uint32_t* b) {
    asm volatile(
        "mma.sync.aligned.m16n8k16.row.col.f32.bf16.bf16.f32 "
        "{%0,%1,%2,%3}, {%4,%5,%6,%7}, {%8,%9}, {%0,%1,%2,%3};"
        : "+f"(c[0]), "+f"(c[1]), "+f"(c[2]), "+f"(c[3])
        : "r"(a[0]), "r"(a[1]), "r"(a[2]), "r"(a[3]), "r"(b[0]), "r"(b[1]));
}
__device__ __forceinline__ void cp16(void* smem, const void* gmem) {
    unsigned s = (unsigned)__cvta_generic_to_shared(smem);
    asm volatile("cp.async.cg.shared.global [%0], [%1], 16;" :: "r"(s), "l"(gmem));
}
#define CP_COMMIT asm volatile("cp.async.commit_group;")
#define CP_WAIT1  asm volatile("cp.async.wait_group 1;")
#define CP_WAIT0  asm volatile("cp.async.wait_group 0;")
__device__ __forceinline__ uint32_t lds32(const bf16* p) { return *(const uint32_t*)p; }

#define PAD 24
#define PLANE_ELT (128 * PAD)            /* bf16 elems per plane: 3072 */
#define GEMM_SMEM (12 * PLANE_ELT * 2)   /* 3 stages x 2 planes x 2 tensors = 73728 B */

// ---------------- prep kernels ----------------------------------------------------
__global__ void k_split(const float* __restrict__ ze,
                        const float* __restrict__ books) {
    const int MZ = M_TOT * D_;
    const int BK = KS_ * D_;
    int stride = gridDim.x * blockDim.x;
    for (int i = blockIdx.x * blockDim.x + threadIdx.x; i < MZ; i += stride) {
        float v = ze[i];
        bf16 hi = __float2bfloat16(v);
        g_ze0[i] = hi;
        g_ze1[i] = __float2bfloat16(v - __bfloat162float(hi));
    }
    for (int i = blockIdx.x * blockDim.x + threadIdx.x; i < BK; i += stride) {
        float v = books[i];
        bf16 hi = __float2bfloat16(v);
        g_bk0[i] = hi;
        g_bk1[i] = __float2bfloat16(v - __bfloat162float(hi));
    }
    for (int j = blockIdx.x * blockDim.x + threadIdx.x; j < BK; j += stride) {
        int d = j / KS_, k = j - d * KS_;
        float v = books[(size_t)k * D_ + d];
        bf16 hi = __float2bfloat16(v);
        g_bkT0[j] = hi;
        g_bkT1[j] = __float2bfloat16(v - __bfloat162float(hi));
    }
}

__global__ void k_norms(const float* __restrict__ books) {
    int warps = (gridDim.x * blockDim.x) >> 5;
    int w     = (blockIdx.x * blockDim.x + threadIdx.x) >> 5;
    int lane  = threadIdx.x & 31;
    for (int r = w; r < KS_; r += warps) {
        const float4* p = (const float4*)(books + (size_t)r * D_);
        float s = 0.0f;
#pragma unroll
        for (int j = 0; j < 2; j++) {
            float4 v = p[lane + j * 32];
            s += v.x * v.x + v.y * v.y + v.z * v.z + v.w * v.w;
        }
#pragma unroll
        for (int o = 16; o; o >>= 1) s += __shfl_xor_sync(0xffffffffu, s, o);
        if (lane == 0) g_b2[r] = s;
    }
}

__global__ void k_scalars(const float* __restrict__ lpq,
                          const float* __restrict__ lpqc,
                          float* __restrict__ out_scalar) {
    float pq   = 1.0f + expf(lpq[0]);
    float prec = 0.5f / fmaxf(pq, 1e-10f);
    float pqc  = 1.0f + expf(lpqc[0]);
    float precc= 0.5f / fmaxf(pqc, 1e-10f);
    g_prec[0] = prec;
    g_prec[1] = precc;
    out_scalar[0] = prec;
}

__global__ void k_cprobs(const float* __restrict__ c_logits,
                         uint32_t k0, uint32_t k1) {
    __shared__ float lg[256];
    int t = threadIdx.x;
    float u = bits_to_unit(d_bits32(k0, k1, (uint32_t)t));
    float pqc = g_prec[1];
    lg[t] = (c_logits[t] * pqc + gumbel_of(u)) * 2.0f;
    __syncthreads();
    if (t < 16) {
        float mx = -1e30f;
        for (int j = 0; j < 16; j++) mx = fmaxf(mx, lg[t * 16 + j]);
        float e[16], sm = 0.0f;
        for (int j = 0; j < 16; j++) { e[j] = expf(lg[t * 16 + j] - mx); sm += e[j]; }
        for (int j = 0; j < 16; j++) g_cprobs[t * 16 + j] = e[j] / sm;
    }
}

// ---- shared GEMM body pieces -----------------------------------------------------
#define FRAG_LOADS(sA, sB, stoff)                                                 \
    do {                                                                          \
        const bf16* A0 = sA + (stoff);                                            \
        const bf16* A1 = A0 + PLANE_ELT;                                          \
        const bf16* B0 = sB + (stoff);                                            \
        const bf16* B1 = B0 + PLANE_ELT;                                          \
        _Pragma("unroll")                                                         \
        for (int f = 0; f < 4; f++) {                                             \
            int r = wm * 64 + f * 16 + gr;                                        \
            a0[f][0] = lds32(&A0[r * PAD + 2 * ct]);                              \
            a0[f][1] = lds32(&A0[(r + 8) * PAD + 2 * ct]);                        \
            a0[f][2] = lds32(&A0[r * PAD + 2 * ct + 8]);                          \
            a0[f][3] = lds32(&A0[(r + 8) * PAD + 2 * ct + 8]);                    \
            a1[f][0] = lds32(&A1[r * PAD + 2 * ct]);                              \
            a1[f][1] = lds32(&A1[(r + 8) * PAD + 2 * ct]);                        \
            a1[f][2] = lds32(&A1[r * PAD + 2 * ct + 8]);                          \
            a1[f][3] = lds32(&A1[(r + 8) * PAD + 2 * ct + 8]);                    \
        }                                                                         \
        _Pragma("unroll")                                                         \
        for (int j = 0; j < 4; j++) {                                             \
            int n = wn * 32 + j * 8 + gr;                                         \
            b0[j][0] = lds32(&B0[n * PAD + 2 * ct]);                              \
            b0[j][1] = lds32(&B0[n * PAD + 2 * ct + 8]);                          \
            b1[j][0] = lds32(&B1[n * PAD + 2 * ct]);                              \
            b1[j][1] = lds32(&B1[n * PAD + 2 * ct + 8]);                          \
        }                                                                         \
    } while (0)

#define MMA_3TERM                                                                 \
    do {                                                                          \
        _Pragma("unroll")                                                         \
        for (int f = 0; f < 4; f++)                                               \
            _Pragma("unroll")                                                     \
            for (int j = 0; j < 4; j++) {                                         \
                mma_bf16(acc[f][j], a0[f], b0[j]);                                \
                mma_bf16(acc[f][j], a0[f], b1[j]);                                \
                mma_bf16(acc[f][j], a1[f], b0[j]);                                \
            }                                                                     \
    } while (0)

// ============ GEMM1 (bf16x2 TC, 3-term, 3-stage): scratch = (2*ze.booksT - b2)*prec
__global__ __launch_bounds__(256)
void k_gemm1_bf(void) {
    extern __shared__ __align__(16) bf16 dsm[];
    bf16* sA = dsm;                       // 3 stages x 2 planes
    bf16* sB = dsm + 6 * PLANE_ELT;
    const int t = threadIdx.x;
    const int m0 = blockIdx.y * 128, n0 = blockIdx.x * 128;
    const int wid = t >> 5, lane = t & 31;
    const int wm = wid & 1, wn = wid >> 1;
    const int gr = lane >> 2, ct = lane & 3;

    float acc[4][4][4] = {};

    auto issue = [&](int kt, int st) {
#pragma unroll
        for (int i = 0; i < 4; i++) {
            int c   = t + i * 256;
            int ab  = c >> 9;
            int pl  = (c >> 8) & 1;
            int row = (c >> 1) & 127;
            int ch  = c & 1;
            bf16* dst = (ab ? sB : sA) + (st * 2 + pl) * PLANE_ELT + row * PAD + ch * 8;
            if (ab == 0) {
                const bf16* src = (pl ? g_ze1 : g_ze0) + (size_t)(m0 + row) * D_ + kt * 16 + ch * 8;
                cp16(dst, src);
            } else {
                const bf16* src = (pl ? g_bk1 : g_bk0) + (size_t)(n0 + row) * D_ + kt * 16 + ch * 8;
                cp16(dst, src);
            }
        }
        CP_COMMIT;
    };

    const int T = D_ / 16;        // 16
    issue(0, 0);
    issue(1, 1);
    for (int kt = 0; kt < T; kt++) {
        if (kt + 1 < T) { CP_WAIT1; } else { CP_WAIT0; }
        __syncthreads();
        if (kt + 2 < T) issue(kt + 2, (kt + 2) % 3);
        const int stoff = (kt % 3) * 2 * PLANE_ELT;
        uint32_t a0[4][4], a1[4][4], b0[4][2], b1[4][2];
        FRAG_LOADS(sA, sB, stoff);
        MMA_3TERM;
    }

    const float prec = g_prec[0];
#pragma unroll
    for (int f = 0; f < 4; f++) {
        int m = m0 + wm * 64 + f * 16 + gr;
#pragma unroll
        for (int j = 0; j < 4; j++) {
            int n = n0 + wn * 32 + j * 8 + ct * 2;
            float b2x = g_b2[n], b2y = g_b2[n + 1];
            float2 v0, v1;
            v0.x = (2.0f * acc[f][j][0] - b2x) * prec;
            v0.y = (2.0f * acc[f][j][1] - b2y) * prec;
            v1.x = (2.0f * acc[f][j][2] - b2x) * prec;
            v1.y = (2.0f * acc[f][j][3] - b2y) * prec;
            *(float2*)(g_scratch + (size_t)m * KS_ + n)       = v0;
            *(float2*)(g_scratch + (size_t)(m + 8) * KS_ + n) = v1;
        }
    }
}

// ============ k_soft512: 16 warps, one k each; fused logits softmax ===============
__global__ __launch_bounds__(512)
void k_soft512(float* __restrict__ prob, float* __restrict__ logp,
               uint32_t k0, uint32_t k1) {
    __shared__ float s_wl[K_][S_];
    __shared__ float red[16];
    const int n = blockIdx.x;
    const int b = blockIdx.y;
    const int t = threadIdx.x;
    const int k = t >> 5, lane = t & 31;
    const size_t row = (size_t)b * N_ + n;
    const float cp = g_cprobs[b * K_ + k];
    const size_t base = (row * K_ + k) * (size_t)S_;

    float y[16];
    float mx = -1e30f;
#pragma unroll
    for (int j = 0; j < 4; j++) {
        int s4 = j * 128 + lane * 4;
        float4 lg = *(const float4*)(g_scratch + base + s4);
        uint32_t ia = (uint32_t)base + (uint32_t)s4;
        float4 wl4;
#pragma unroll
        for (int e = 0; e < 4; e++) {
            float la = (&lg.x)[e];
            float g  = gumbel_of(bits_to_unit(d_bits32(k0, k1, ia + e)));
            float yy = (la + g) * 2.0f;
            y[j * 4 + e] = yy;
            (&wl4.x)[e] = cp * la;
            mx = fmaxf(mx, yy);
        }
        *(float4*)(&s_wl[k][s4]) = wl4;
    }
#pragma unroll
    for (int o = 16; o; o >>= 1) mx = fmaxf(mx, __shfl_xor_sync(0xffffffffu, mx, o));
    float sum = 0.0f;
#pragma unroll
    for (int i = 0; i < 16; i++) { y[i] = __expf(y[i] - mx); sum += y[i]; }
#pragma unroll
    for (int o = 16; o; o >>= 1) sum += __shfl_xor_sync(0xffffffffu, sum, o);
    const float f = cp / sum;
#pragma unroll
    for (int j = 0; j < 4; j++) {
        int s4 = j * 128 + lane * 4;
        float v0 = y[j*4+0] * f, v1 = y[j*4+1] * f, v2 = y[j*4+2] * f, v3 = y[j*4+3] * f;
        bf16 h0 = __float2bfloat16(v0), h1 = __float2bfloat16(v1);
        bf16 h2 = __float2bfloat16(v2), h3 = __float2bfloat16(v3);
        bf16 l0 = __float2bfloat16(v0 - __bfloat162float(h0));
        bf16 l1 = __float2bfloat16(v1 - __bfloat162float(h1));
        bf16 l2 = __float2bfloat16(v2 - __bfloat162float(h2));
        bf16 l3 = __float2bfloat16(v3 - __bfloat162float(h3));
        uint32_t p0  = (uint32_t)__bfloat16_as_ushort(h0) | ((uint32_t)__bfloat16_as_ushort(h1) << 16);
        uint32_t p1_ = (uint32_t)__bfloat16_as_ushort(h2) | ((uint32_t)__bfloat16_as_ushort(h3) << 16);
        uint32_t q0  = (uint32_t)__bfloat16_as_ushort(l0) | ((uint32_t)__bfloat16_as_ushort(l1) << 16);
        uint32_t q1_ = (uint32_t)__bfloat16_as_ushort(l2) | ((uint32_t)__bfloat16_as_ushort(l3) << 16);
        *(uint2*)(g_w0 + base + s4) = make_uint2(p0, p1_);
        *(uint2*)(g_w1 + base + s4) = make_uint2(q0, q1_);
    }

    __syncthreads();
    float wl = 0.0f;
#pragma unroll
    for (int kk = 0; kk < K_; kk++) wl += s_wl[kk][t];

    float m_ = wl;
#pragma unroll
    for (int o = 16; o; o >>= 1) m_ = fmaxf(m_, __shfl_xor_sync(0xffffffffu, m_, o));
    if (lane == 0) red[k] = m_;
    __syncthreads();
    float M = red[0];
#pragma unroll
    for (int w = 1; w < 16; w++) M = fmaxf(M, red[w]);
    float e = __expf(wl - M);
    float z_ = e;
#pragma unroll
    for (int o = 16; o; o >>= 1) z_ += __shfl_xor_sync(0xffffffffu, z_, o);
    __syncthreads();
    if (lane == 0) red[k] = z_;
    __syncthreads();
    float Z = 0.0f;
#pragma unroll
    for (int w = 0; w < 16; w++) Z += red[w];
    float lz = __logf(Z);

    size_t p0 = row * S_;
    prob[p0 + t] = e / Z;
    logp[p0 + t] = (wl - M) - lz;
}

// ============ GEMM2 (bf16x2 TC, 3-term, 3-stage): zq = W @ books ==================
__global__ __launch_bounds__(256)
void k_gemm2_bf(float* __restrict__ zq) {
    extern __shared__ __align__(16) bf16 dsm[];
    bf16* sA = dsm;
    bf16* sB = dsm + 6 * PLANE_ELT;
    const int t = threadIdx.x;
    const int m0 = blockIdx.y * 128, n0 = blockIdx.x * 128;
    const int wid = t >> 5, lane = t & 31;
    const int wm = wid & 1, wn = wid >> 1;
    const int gr = lane >> 2, ct = lane & 3;

    float acc[4][4][4] = {};

    auto issue = [&](int kt, int st) {
#pragma unroll
        for (int i = 0; i < 4; i++) {
            int c   = t + i * 256;
            int ab  = c >> 9;
            int pl  = (c >> 8) & 1;
            int row = (c >> 1) & 127;
            int ch  = c & 1;
            bf16* dst = (ab ? sB : sA) + (st * 2 + pl) * PLANE_ELT + row * PAD + ch * 8;
            if (ab == 0) {
                const bf16* src = (pl ? g_w1 : g_w0) + (size_t)(m0 + row) * KS_ + kt * 16 + ch * 8;
                cp16(dst, src);
            } else {
                const bf16* src = (pl ? g_bkT1 : g_bkT0) + (size_t)(n0 + row) * KS_ + kt * 16 + ch * 8;
                cp16(dst, src);
            }
        }
        CP_COMMIT;
    };

    const int T = KS_ / 16;       // 512
    issue(0, 0);
    issue(1, 1);
    for (int kt = 0; kt < T; kt++) {
        if (kt + 1 < T) { CP_WAIT1; } else { CP_WAIT0; }
        __syncthreads();
        if (kt + 2 < T) issue(kt + 2, (kt + 2) % 3);
        const int stoff = (kt % 3) * 2 * PLANE_ELT;
        uint32_t a0[4][4], a1[4][4], b0[4][2], b1[4][2];
        FRAG_LOADS(sA, sB, stoff);
        MMA_3TERM;
    }

#pragma unroll
    for (int f = 0; f < 4; f++) {
        int m = m0 + wm * 64 + f * 16 + gr;
#pragma unroll
        for (int j = 0; j < 4; j++) {
            int n = n0 + wn * 32 + j * 8 + ct * 2;
            *(float2*)(zq + (size_t)m * D_ + n)       = make_float2(acc[f][j][0], acc[f][j][1]);
            *(float2*)(zq + (size_t)(m + 8) * D_ + n) = make_float2(acc[f][j][2], acc[f][j][3]);
        }
    }
}

// ---------------- host-side threefry ----------------------------------------------
static void h_tf(uint32_t k0, uint32_t k1, uint32_t x0, uint32_t x1,
                 uint32_t* o0, uint32_t* o1) {
    uint32_t ks2 = k0 ^ k1 ^ 0x1BD11BDAu;
    x0 += k0; x1 += k1;
    const int ra[4] = {13, 15, 26, 6}, rb[4] = {17, 29, 16, 24};
#define HR(r) { x0 += x1; x1 = (x1 << (r)) | (x1 >> (32 - (r))); x1 ^= x0; }
    for (int i = 0; i < 4; i++) HR(ra[i]); x0 += k1;  x1 += ks2 + 1u;
    for (int i = 0; i < 4; i++) HR(rb[i]); x0 += ks2; x1 += k0  + 2u;
    for (int i = 0; i < 4; i++) HR(ra[i]); x0 += k0;  x1 += k1  + 3u;
    for (int i = 0; i < 4; i++) HR(rb[i]); x0 += k1;  x1 += ks2 + 4u;
    for (int i = 0; i < 4; i++) HR(ra[i]); x0 += ks2; x1 += k0  + 5u;
#undef HR
    *o0 = x0; *o1 = x1;
}

extern "C" void kernel_launch(void* const* d_in, const int* in_sizes, int n_in,
                              void* d_out, int out_size) {
    const float* ze       = (const float*)d_in[0];
    const float* c_logits = (const float*)d_in[1];
    const float* books    = (const float*)d_in[2];
    const float* lpq      = (const float*)d_in[3];
    const float* lpqc     = (const float*)d_in[4];

    float* out     = (float*)d_out;
    float* zq      = out;
    float* pscalar = out + ZQ_SIZE;
    float* prob    = pscalar + 1;
    float* logp    = prob + PROB_SIZE;

    uint32_t kg1_0, kg1_1, kg2_0, kg2_1;
    h_tf(0u, 42u, 0u, 0u, &kg1_0, &kg1_1);
    h_tf(0u, 42u, 0u, 1u, &kg2_0, &kg2_1);

    cudaFuncSetAttribute(k_gemm1_bf, cudaFuncAttributeMaxDynamicSharedMemorySize, GEMM_SMEM);
    cudaFuncSetAttribute(k_gemm2_bf, cudaFuncAttributeMaxDynamicSharedMemorySize, GEMM_SMEM);

    // order chosen so the ncu capture slot (launch index 3) lands on k_gemm1_bf
    k_split<<<1024, 256>>>(ze, books);                             // 0
    k_norms<<<64, 256>>>(books);                                   // 1
    k_scalars<<<1, 1>>>(lpq, lpqc, pscalar);                       // 2
    k_gemm1_bf<<<dim3(KS_ / 128, M_TOT / 128), 256, GEMM_SMEM>>>();// 3 (profiled)
    k_cprobs<<<1, 256>>>(c_logits, kg1_0, kg1_1);                  // 4
    k_soft512<<<dim3(N_, B_), 512>>>(prob, logp, kg2_0, kg2_1);    // 5
    k_gemm2_bf<<<dim3(D_ / 128, M_TOT / 128), 256, GEMM_SMEM>>>(zq); // 6
}